// round 15
// baseline (speedup 1.0000x reference)
#include <cuda_runtime.h>
#include <cuda_bf16.h>
#include <cuda_fp16.h>

#define T_DIM 64
#define B_DIM 16
#define S_DIM 256
#define D_DIM 512

// scratch: h as half, (B, T, D)
__device__ __half2 g_h16[B_DIM * T_DIM * D_DIM / 2];
// scratch: context as half, (B, S, D)
__device__ __half2 g_c16[B_DIM * S_DIM * D_DIM / 2];
// scratch: split-K partials, remapped (B*T, D)
__device__ float g_hp[2][T_DIM * B_DIM * D_DIM];

__device__ __forceinline__ __half2 tanh2_ap(__half2 x) {
    unsigned xi = *(unsigned*)&x;
    unsigned yi;
    asm("tanh.approx.f16x2 %0, %1;" : "=r"(yi) : "r"(xi));
    return *(__half2*)&yi;
}

#define BAR_ARRIVE(id, cnt) asm volatile("bar.arrive %0, %1;" :: "r"(id), "r"(cnt) : "memory")
#define BAR_SYNC(id, cnt)   asm volatile("bar.sync %0, %1;"   :: "r"(id), "r"(cnt) : "memory")

// ---------------------------------------------------------------------------
// Kernel 0: context fp32 -> half2.
// ---------------------------------------------------------------------------
__global__ __launch_bounds__(256) void conv_kernel(const float* __restrict__ src)
{
    const int i = blockIdx.x * 256 + threadIdx.x;
    const float4 a = ((const float4*)src)[2 * i];
    const float4 b = ((const float4*)src)[2 * i + 1];
    __half2 out[4];
    out[0] = __floats2half2_rn(a.x, a.y);
    out[1] = __floats2half2_rn(a.z, a.w);
    out[2] = __floats2half2_rn(b.x, b.y);
    out[3] = __floats2half2_rn(b.z, b.w);
    ((uint4*)g_c16)[i] = *(const uint4*)out;
}

// ---------------------------------------------------------------------------
// Kernel 1: split-K gemm (R12-proven). grid (8,16,2)=256 blocks.
// ---------------------------------------------------------------------------
__global__ __launch_bounds__(256, 2) void gemm_kernel(
    const float* __restrict__ A,
    const float* __restrict__ W)
{
    __shared__ float As[2][64][33];
    __shared__ float Bs[2][32][68];

    const int tid = threadIdx.x;
    const int tx = tid & 15;
    const int ty = tid >> 4;
    const int m0 = blockIdx.y * 64;
    const int n0 = blockIdx.x * 64;
    const int kb = blockIdx.z * 256;
    const int ke = kb + 256;

    const int ar0 = tid >> 3,         ac0 = (tid & 7) * 4;
    const int ar1 = (tid + 256) >> 3, ac1 = ((tid + 256) & 7) * 4;
    const int br0 = tid >> 4,         bc0 = (tid & 15) * 4;
    const int br1 = (tid + 256) >> 4, bc1 = ((tid + 256) & 15) * 4;

    float acc[4][4];
#pragma unroll
    for (int i = 0; i < 4; ++i)
#pragma unroll
        for (int j = 0; j < 4; ++j) acc[i][j] = 0.f;

    {
        float4 a0 = *(const float4*)&A[(size_t)(m0 + ar0) * D_DIM + kb + ac0];
        float4 a1 = *(const float4*)&A[(size_t)(m0 + ar1) * D_DIM + kb + ac1];
        float4 b0 = *(const float4*)&W[(size_t)(kb + br0) * D_DIM + n0 + bc0];
        float4 b1 = *(const float4*)&W[(size_t)(kb + br1) * D_DIM + n0 + bc1];
        As[0][ar0][ac0 + 0] = a0.x; As[0][ar0][ac0 + 1] = a0.y;
        As[0][ar0][ac0 + 2] = a0.z; As[0][ar0][ac0 + 3] = a0.w;
        As[0][ar1][ac1 + 0] = a1.x; As[0][ar1][ac1 + 1] = a1.y;
        As[0][ar1][ac1 + 2] = a1.z; As[0][ar1][ac1 + 3] = a1.w;
        *(float4*)&Bs[0][br0][bc0] = b0;
        *(float4*)&Bs[0][br1][bc1] = b1;
    }
    __syncthreads();

    int buf = 0;
    for (int k0 = kb; k0 < ke; k0 += 32) {
        const bool has_next = (k0 + 32) < ke;
        float4 a0, a1, b0, b1;
        if (has_next) {
            const int kn = k0 + 32;
            a0 = *(const float4*)&A[(size_t)(m0 + ar0) * D_DIM + kn + ac0];
            a1 = *(const float4*)&A[(size_t)(m0 + ar1) * D_DIM + kn + ac1];
            b0 = *(const float4*)&W[(size_t)(kn + br0) * D_DIM + n0 + bc0];
            b1 = *(const float4*)&W[(size_t)(kn + br1) * D_DIM + n0 + bc1];
        }

#pragma unroll
        for (int k = 0; k < 32; ++k) {
            float4 b4 = *(const float4*)&Bs[buf][k][tx * 4];
            float x0 = As[buf][ty * 4 + 0][k];
            float x1 = As[buf][ty * 4 + 1][k];
            float x2 = As[buf][ty * 4 + 2][k];
            float x3 = As[buf][ty * 4 + 3][k];
            acc[0][0] += x0 * b4.x; acc[0][1] += x0 * b4.y; acc[0][2] += x0 * b4.z; acc[0][3] += x0 * b4.w;
            acc[1][0] += x1 * b4.x; acc[1][1] += x1 * b4.y; acc[1][2] += x1 * b4.z; acc[1][3] += x1 * b4.w;
            acc[2][0] += x2 * b4.x; acc[2][1] += x2 * b4.y; acc[2][2] += x2 * b4.z; acc[2][3] += x2 * b4.w;
            acc[3][0] += x3 * b4.x; acc[3][1] += x3 * b4.y; acc[3][2] += x3 * b4.z; acc[3][3] += x3 * b4.w;
        }

        if (has_next) {
            const int nb = buf ^ 1;
            As[nb][ar0][ac0 + 0] = a0.x; As[nb][ar0][ac0 + 1] = a0.y;
            As[nb][ar0][ac0 + 2] = a0.z; As[nb][ar0][ac0 + 3] = a0.w;
            As[nb][ar1][ac1 + 0] = a1.x; As[nb][ar1][ac1 + 1] = a1.y;
            As[nb][ar1][ac1 + 2] = a1.z; As[nb][ar1][ac1 + 3] = a1.w;
            *(float4*)&Bs[nb][br0][bc0] = b0;
            *(float4*)&Bs[nb][br1][bc1] = b1;
        }
        __syncthreads();
        buf ^= 1;
    }

    float* hp = g_hp[blockIdx.z];
#pragma unroll
    for (int i = 0; i < 4; ++i) {
        int m = m0 + ty * 4 + i;
        int bb = m & (B_DIM - 1);
        int tt = m >> 4;
        float4 o;
        o.x = acc[i][0]; o.y = acc[i][1]; o.z = acc[i][2]; o.w = acc[i][3];
        *(float4*)&hp[((size_t)bb * T_DIM + tt) * D_DIM + n0 + tx * 4] = o;
    }
}

// ---------------------------------------------------------------------------
// Kernel 1b: reduce partials + bias -> fp16 g_h16.
// ---------------------------------------------------------------------------
__global__ __launch_bounds__(256) void reduce_kernel(const float* __restrict__ bias)
{
    const int i = blockIdx.x * 256 + threadIdx.x;
    const int n = (i * 8) & (D_DIM - 1);
    float4 a0 = ((const float4*)g_hp[0])[2 * i];
    float4 a1 = ((const float4*)g_hp[0])[2 * i + 1];
    float4 b0 = ((const float4*)g_hp[1])[2 * i];
    float4 b1 = ((const float4*)g_hp[1])[2 * i + 1];
    float4 c0 = *(const float4*)&bias[n];
    float4 c1 = *(const float4*)&bias[n + 4];
    __half2 out[4];
    out[0] = __floats2half2_rn(a0.x + b0.x + c0.x, a0.y + b0.y + c0.y);
    out[1] = __floats2half2_rn(a0.z + b0.z + c0.z, a0.w + b0.w + c0.w);
    out[2] = __floats2half2_rn(a1.x + b1.x + c1.x, a1.y + b1.y + c1.y);
    out[3] = __floats2half2_rn(a1.z + b1.z + c1.z, a1.w + b1.w + c1.w);
    ((uint4*)g_h16)[i] = *(const uint4*)out;
}

// ---------------------------------------------------------------------------
// Kernel 2: FUSED logits + online-softmax + AV. grid=(B, T/4)=256 blocks,
// 384 threads, 2 CTA/SM.
//   warps 0..7  (producers): tanh logits, chunk-ordered over s (8 chunks of
//                32); each warp does 4 s per chunk; bar.arrive(k,384) when
//                chunk k's logits are in lg[][]. Final: exact out_attn.
//   warps 8..11 (consumers): warp 8 runs online softmax per chunk (running
//                m/Z, p~ = exp(l-m_k) to pc[buf]), all 4 warps do rescaled AV
//                accumulation over d (128 thr x 4d). bar 8 = consumer-internal,
//                bar 9 = warp8 -> producers handoff of m_fin / 1/Z.
// ---------------------------------------------------------------------------
__global__ __launch_bounds__(384, 2) void attn_fused(
    const float* __restrict__ v_w,
    const float* __restrict__ values,
    float* __restrict__ out_attn,
    float* __restrict__ out_w)
{
    __shared__ float lg[4][S_DIM];      // raw logits, 4 KB
    __shared__ float pc[2][4][32];      // chunk probs (unnormalized), 1 KB
    __shared__ float scs[2][4];         // per-chunk rescale factors
    __shared__ float mfin[4], zinv[4];

    const int b    = blockIdx.x;
    const int t0   = blockIdx.y * 4;
    const int tid  = threadIdx.x;
    const int wid  = tid >> 5;
    const int lane = tid & 31;

    if (wid < 8) {
        // ================= PRODUCERS =================
        __half2 hh[4][8];
        __half2 ww[8];
        {
            const uint4* hp = (const uint4*)(g_h16 + ((size_t)b * T_DIM + t0) * (D_DIM / 2));
#pragma unroll
            for (int t = 0; t < 4; ++t) {
                uint4 u0 = hp[t * (D_DIM / 8) + lane * 2];
                uint4 u1 = hp[t * (D_DIM / 8) + lane * 2 + 1];
                *(uint4*)&hh[t][0] = u0;
                *(uint4*)&hh[t][4] = u1;
            }
            const float4* vw4 = (const float4*)v_w;
#pragma unroll
            for (int j = 0; j < 4; ++j) {
                float4 w = vw4[lane * 4 + j];
                ww[j * 2 + 0] = __floats2half2_rn(w.x, w.y);
                ww[j * 2 + 1] = __floats2half2_rn(w.z, w.w);
            }
        }

        const uint4* cb = (const uint4*)(g_c16 + (size_t)b * S_DIM * (D_DIM / 2)) + lane * 2;
        {
            const int sfirst = wid * 4;
            uint4 cu0 = cb[(size_t)sfirst * (D_DIM / 8)];
            uint4 cu1 = cb[(size_t)sfirst * (D_DIM / 8) + 1];

            for (int k = 0; k < 8; ++k) {
#pragma unroll
                for (int j = 0; j < 4; ++j) {
                    const int scur = k * 32 + wid * 4 + j;
                    const int snxt = (j < 3) ? (scur + 1)
                                   : (k < 7 ? (k + 1) * 32 + wid * 4 : scur);
                    uint4 nu0 = cb[(size_t)snxt * (D_DIM / 8)];
                    uint4 nu1 = cb[(size_t)snxt * (D_DIM / 8) + 1];

                    __half2 cc[8];
                    *(uint4*)&cc[0] = cu0;
                    *(uint4*)&cc[4] = cu1;

                    float acc[4];
#pragma unroll
                    for (int t = 0; t < 4; ++t) {
                        __half2 p[8];
#pragma unroll
                        for (int jj = 0; jj < 8; ++jj)
                            p[jj] = __hmul2(tanh2_ap(__hadd2(hh[t][jj], cc[jj])), ww[jj]);
                        __half2 q0 = __hadd2(p[0], p[1]);
                        __half2 q1 = __hadd2(p[2], p[3]);
                        __half2 q2 = __hadd2(p[4], p[5]);
                        __half2 q3 = __hadd2(p[6], p[7]);
                        float a = (__low2float(q0) + __high2float(q0))
                                + (__low2float(q1) + __high2float(q1));
                        float c = (__low2float(q2) + __high2float(q2))
                                + (__low2float(q3) + __high2float(q3));
                        acc[t] = a + c;
                    }

                    // merged 9-shfl butterfly: lanes 0,16,8,24 -> t 0,1,2,3
                    float r0 = acc[0] + __shfl_xor_sync(0xffffffffu, acc[0], 16);
                    float r1 = acc[1] + __shfl_xor_sync(0xffffffffu, acc[1], 16);
                    float r2 = acc[2] + __shfl_xor_sync(0xffffffffu, acc[2], 16);
                    float r3 = acc[3] + __shfl_xor_sync(0xffffffffu, acc[3], 16);
                    float m01 = (lane & 16) ? r1 : r0;
                    float m23 = (lane & 16) ? r3 : r2;
                    m01 += __shfl_xor_sync(0xffffffffu, m01, 8);
                    m23 += __shfl_xor_sync(0xffffffffu, m23, 8);
                    float qv = (lane & 8) ? m23 : m01;
                    qv += __shfl_xor_sync(0xffffffffu, qv, 4);
                    qv += __shfl_xor_sync(0xffffffffu, qv, 2);
                    qv += __shfl_xor_sync(0xffffffffu, qv, 1);
                    if ((lane & 7) == 0) {
                        int t = ((lane >> 4) & 1) + (((lane >> 3) & 1) << 1);
                        lg[t][scur] = qv;
                    }
                    cu0 = nu0; cu1 = nu1;
                }
                BAR_ARRIVE(k, 384);
            }
        }

        // wait for final m/Z from warp 8, then emit exact attn probs
        BAR_SYNC(9, 288);
        {
            const int t  = tid >> 6;          // 0..3
            const int s0 = (tid & 63) * 4;
            float4 l4 = *(const float4*)&lg[t][s0];
            const float mf = mfin[t];
            const float zi = zinv[t];
            float4 o;
            o.x = __expf(l4.x - mf) * zi;
            o.y = __expf(l4.y - mf) * zi;
            o.z = __expf(l4.z - mf) * zi;
            o.w = __expf(l4.w - mf) * zi;
            *(float4*)&out_attn[((size_t)b * T_DIM + t0 + t) * S_DIM + s0] = o;
        }
    } else {
        // ================= CONSUMERS =================
        const int ctid = tid - 256;           // 0..127
        const float* vp = values + (size_t)b * S_DIM * D_DIM + ctid * 4;

        float w[4][4];
#pragma unroll
        for (int t = 0; t < 4; ++t)
#pragma unroll
            for (int j = 0; j < 4; ++j) w[t][j] = 0.f;
        float m[4], Z[4];
#pragma unroll
        for (int t = 0; t < 4; ++t) { m[t] = -1e30f; Z[t] = 0.f; }

        float4 v = *(const float4*)&vp[0];

        for (int k = 0; k < 8; ++k) {
            BAR_SYNC(k, 384);                 // chunk k logits ready
            const int buf = k & 1;

            if (wid == 8) {
#pragma unroll
                for (int t = 0; t < 4; ++t) {
                    float l = lg[t][k * 32 + lane];
                    float mx = l;
#pragma unroll
                    for (int o = 16; o; o >>= 1)
                        mx = fmaxf(mx, __shfl_xor_sync(0xffffffffu, mx, o));
                    float mn  = fmaxf(m[t], mx);
                    float sct = __expf(m[t] - mn);
                    float p   = __expf(l - mn);
                    float sum = p;
#pragma unroll
                    for (int o = 16; o; o >>= 1)
                        sum += __shfl_xor_sync(0xffffffffu, sum, o);
                    Z[t] = Z[t] * sct + sum;
                    m[t] = mn;
                    pc[buf][t][lane] = p;
                    if (lane == 0) scs[buf][t] = sct;
                }
                if (k == 7) {
                    if (lane == 0) {
#pragma unroll
                        for (int t = 0; t < 4; ++t) {
                            mfin[t] = m[t];
                            zinv[t] = 1.0f / Z[t];
                        }
                    }
                    BAR_ARRIVE(9, 288);       // hand m_fin/1Z to producers
                }
            }
            BAR_SYNC(8, 128);                 // pc/scs[buf] ready

            const float sc0 = scs[buf][0];
            const float sc1 = scs[buf][1];
            const float sc2 = scs[buf][2];
            const float sc3 = scs[buf][3];
#pragma unroll
            for (int j = 0; j < 4; ++j) {
                w[0][j] *= sc0; w[1][j] *= sc1;
                w[2][j] *= sc2; w[3][j] *= sc3;
            }

#pragma unroll
            for (int s = 0; s < 32; ++s) {
                const int sg = k * 32 + s;
                float4 vn;
                if (sg < S_DIM - 1)
                    vn = *(const float4*)&vp[(size_t)(sg + 1) * D_DIM];
                float p0 = pc[buf][0][s];
                float p1 = pc[buf][1][s];
                float p2 = pc[buf][2][s];
                float p3 = pc[buf][3][s];
                w[0][0] += p0 * v.x; w[0][1] += p0 * v.y; w[0][2] += p0 * v.z; w[0][3] += p0 * v.w;
                w[1][0] += p1 * v.x; w[1][1] += p1 * v.y; w[1][2] += p1 * v.z; w[1][3] += p1 * v.w;
                w[2][0] += p2 * v.x; w[2][1] += p2 * v.y; w[2][2] += p2 * v.z; w[2][3] += p2 * v.w;
                w[3][0] += p3 * v.x; w[3][1] += p3 * v.y; w[3][2] += p3 * v.z; w[3][3] += p3 * v.w;
                v = vn;
            }
        }

        // epilogue: divide by Z, store
#pragma unroll
        for (int t = 0; t < 4; ++t) {
            const float zi = zinv[t];         // written before bar8(k=7)
            float4 o;
            o.x = w[t][0] * zi; o.y = w[t][1] * zi;
            o.z = w[t][2] * zi; o.w = w[t][3] * zi;
            *(float4*)&out_w[((size_t)(t0 + t) * B_DIM + b) * D_DIM + ctid * 4] = o;
        }
    }
}

// ---------------------------------------------------------------------------
extern "C" void kernel_launch(void* const* d_in, const int* in_sizes, int n_in,
                              void* d_out, int out_size) {
    const float* input   = (const float*)d_in[0];
    const float* context = (const float*)d_in[1];
    const float* values  = (const float*)d_in[2];
    const float* W_comb  = (const float*)d_in[3];
    const float* b_comb  = (const float*)d_in[4];
    const float* v_w     = (const float*)d_in[5];

    float* out_weighted = (float*)d_out;                                 // (T,B,D)
    float* out_attn     = (float*)d_out + (size_t)T_DIM * B_DIM * D_DIM; // (B*T,S)

    const int conv_blocks = (B_DIM * S_DIM * D_DIM / 8) / 256;           // 1024
    conv_kernel<<<conv_blocks, 256>>>(context);

    dim3 g1(D_DIM / 64, (T_DIM * B_DIM) / 64, 2);        // (8,16,2) = 256 blocks
    gemm_kernel<<<g1, 256>>>(input, W_comb);
    reduce_kernel<<<(T_DIM * B_DIM * D_DIM / 8) / 256, 256>>>(b_comb);

    dim3 g2(B_DIM, T_DIM / 4);                           // (16,16) = 256 blocks
    attn_fused<<<g2, 384>>>(v_w, values, out_attn, out_weighted);
}

// round 16
// speedup vs baseline: 1.2203x; 1.2203x over previous
#include <cuda_runtime.h>
#include <cuda_bf16.h>
#include <cuda_fp16.h>

#define T_DIM 64
#define B_DIM 16
#define S_DIM 256
#define D_DIM 512
#define T_TILE 4       // t-rows per logits block
#define T_AV   8       // t-rows per AV block

// scratch: h = input @ W_comb + b_comb as half, stored (B, T, D)
__device__ __half2 g_h16[B_DIM * T_DIM * D_DIM / 2];

__device__ __forceinline__ __half2 tanh2_ap(__half2 x) {
    unsigned xi = *(unsigned*)&x;
    unsigned yi;
    asm("tanh.approx.f16x2 %0, %1;" : "=r"(yi) : "r"(xi));
    return *(__half2*)&yi;
}

// ---------------------------------------------------------------------------
// Kernel 1: h = input @ W + bias (M=1024,N=512,K=512), writes half2 g_h16.
// R5-proven: 64x64 tile, 256 thr, 4x4 microtile, double-buffered SMEM.
// ---------------------------------------------------------------------------
__global__ __launch_bounds__(256, 2) void gemm_kernel(
    const float* __restrict__ A,
    const float* __restrict__ W,
    const float* __restrict__ bias)
{
    __shared__ float As[2][64][33];
    __shared__ float Bs[2][32][68];

    const int tid = threadIdx.x;
    const int tx = tid & 15;
    const int ty = tid >> 4;
    const int m0 = blockIdx.y * 64;
    const int n0 = blockIdx.x * 64;

    const int ar0 = tid >> 3,         ac0 = (tid & 7) * 4;
    const int ar1 = (tid + 256) >> 3, ac1 = ((tid + 256) & 7) * 4;
    const int br0 = tid >> 4,         bc0 = (tid & 15) * 4;
    const int br1 = (tid + 256) >> 4, bc1 = ((tid + 256) & 15) * 4;

    float acc[4][4];
#pragma unroll
    for (int i = 0; i < 4; ++i)
#pragma unroll
        for (int j = 0; j < 4; ++j) acc[i][j] = 0.f;

    {
        float4 a0 = *(const float4*)&A[(size_t)(m0 + ar0) * D_DIM + ac0];
        float4 a1 = *(const float4*)&A[(size_t)(m0 + ar1) * D_DIM + ac1];
        float4 b0 = *(const float4*)&W[(size_t)br0 * D_DIM + n0 + bc0];
        float4 b1 = *(const float4*)&W[(size_t)br1 * D_DIM + n0 + bc1];
        As[0][ar0][ac0 + 0] = a0.x; As[0][ar0][ac0 + 1] = a0.y;
        As[0][ar0][ac0 + 2] = a0.z; As[0][ar0][ac0 + 3] = a0.w;
        As[0][ar1][ac1 + 0] = a1.x; As[0][ar1][ac1 + 1] = a1.y;
        As[0][ar1][ac1 + 2] = a1.z; As[0][ar1][ac1 + 3] = a1.w;
        *(float4*)&Bs[0][br0][bc0] = b0;
        *(float4*)&Bs[0][br1][bc1] = b1;
    }
    __syncthreads();

    int buf = 0;
    for (int k0 = 0; k0 < D_DIM; k0 += 32) {
        const bool has_next = (k0 + 32) < D_DIM;
        float4 a0, a1, b0, b1;
        if (has_next) {
            const int kn = k0 + 32;
            a0 = *(const float4*)&A[(size_t)(m0 + ar0) * D_DIM + kn + ac0];
            a1 = *(const float4*)&A[(size_t)(m0 + ar1) * D_DIM + kn + ac1];
            b0 = *(const float4*)&W[(size_t)(kn + br0) * D_DIM + n0 + bc0];
            b1 = *(const float4*)&W[(size_t)(kn + br1) * D_DIM + n0 + bc1];
        }

#pragma unroll
        for (int k = 0; k < 32; ++k) {
            float4 b4 = *(const float4*)&Bs[buf][k][tx * 4];
            float x0 = As[buf][ty * 4 + 0][k];
            float x1 = As[buf][ty * 4 + 1][k];
            float x2 = As[buf][ty * 4 + 2][k];
            float x3 = As[buf][ty * 4 + 3][k];
            acc[0][0] += x0 * b4.x; acc[0][1] += x0 * b4.y; acc[0][2] += x0 * b4.z; acc[0][3] += x0 * b4.w;
            acc[1][0] += x1 * b4.x; acc[1][1] += x1 * b4.y; acc[1][2] += x1 * b4.z; acc[1][3] += x1 * b4.w;
            acc[2][0] += x2 * b4.x; acc[2][1] += x2 * b4.y; acc[2][2] += x2 * b4.z; acc[2][3] += x2 * b4.w;
            acc[3][0] += x3 * b4.x; acc[3][1] += x3 * b4.y; acc[3][2] += x3 * b4.z; acc[3][3] += x3 * b4.w;
        }

        if (has_next) {
            const int nb = buf ^ 1;
            As[nb][ar0][ac0 + 0] = a0.x; As[nb][ar0][ac0 + 1] = a0.y;
            As[nb][ar0][ac0 + 2] = a0.z; As[nb][ar0][ac0 + 3] = a0.w;
            As[nb][ar1][ac1 + 0] = a1.x; As[nb][ar1][ac1 + 1] = a1.y;
            As[nb][ar1][ac1 + 2] = a1.z; As[nb][ar1][ac1 + 3] = a1.w;
            *(float4*)&Bs[nb][br0][bc0] = b0;
            *(float4*)&Bs[nb][br1][bc1] = b1;
        }
        __syncthreads();
        buf ^= 1;
    }

#pragma unroll
    for (int i = 0; i < 4; ++i) {
        int m = m0 + ty * 4 + i;
        int bb = m & (B_DIM - 1);
        int tt = m >> 4;
        const float b0 = bias[n0 + tx * 4 + 0];
        const float b1 = bias[n0 + tx * 4 + 1];
        const float b2 = bias[n0 + tx * 4 + 2];
        const float b3 = bias[n0 + tx * 4 + 3];
        __half2 h2[2];
        h2[0] = __floats2half2_rn(acc[i][0] + b0, acc[i][1] + b1);
        h2[1] = __floats2half2_rn(acc[i][2] + b2, acc[i][3] + b3);
        __half2* dst = &g_h16[(((size_t)bb * T_DIM + tt) * D_DIM + n0 + tx * 4) / 2];
        *(uint2*)dst = *(const uint2*)h2;
    }
}

// ---------------------------------------------------------------------------
// Kernel 2: logits + softmax, fp16 tanh path (R8-proven, 79.9 bench config).
// grid=(B, T/4)=256 blocks, 512 thr, 2 CTA/SM (single wave).
// Warp w: quarter q=w&3 (128-dim D slice, 4 dims/lane), sg=w>>2 (64 s).
// Context read as fp32 and converted in-loop (no separate conv kernel).
// ---------------------------------------------------------------------------
__global__ __launch_bounds__(512, 2) void logits_kernel(
    const float* __restrict__ context,   // (B,S,D)
    const float* __restrict__ v_w,       // (D)
    float* __restrict__ out_attn)        // (B*T, S) -> normalized probs
{
    __shared__ __half2 h_s[T_TILE * D_DIM / 2];    // 4 KB (fp16 h tile)
    __shared__ float lg[4][T_TILE][S_DIM];         // 16 KB (quarter-partials)

    const int b    = blockIdx.x;
    const int t0   = blockIdx.y * T_TILE;
    const int tid  = threadIdx.x;
    const int wid  = tid >> 5;
    const int lane = tid & 31;
    const int q    = wid & 3;
    const int sg   = wid >> 2;

    {
        const uint4* hp = (const uint4*)(g_h16 + ((size_t)b * T_DIM + t0) * (D_DIM / 2));
        uint4* hs4 = (uint4*)h_s;
        for (int i = tid; i < T_TILE * D_DIM / 8; i += 512) hs4[i] = hp[i];
    }
    __syncthreads();

    // ---- logits ----
    {
        const int dof = q * 32 + lane;       // float4-equivalent idx within D row
        __half2 hh[T_TILE][2];
#pragma unroll
        for (int t = 0; t < T_TILE; ++t) {
            hh[t][0] = h_s[t * (D_DIM / 2) + dof * 2];
            hh[t][1] = h_s[t * (D_DIM / 2) + dof * 2 + 1];
        }
        float4 wf = ((const float4*)v_w)[dof];
        const __half2 ww0 = __floats2half2_rn(wf.x, wf.y);
        const __half2 ww1 = __floats2half2_rn(wf.z, wf.w);

        const float4* cbase = (const float4*)(context + (size_t)b * S_DIM * D_DIM)
                              + (size_t)(sg * 64) * (D_DIM / 4) + dof;

        float4 c0 = cbase[0];
        float4 c1 = cbase[1 * (D_DIM / 4)];

        for (int si = 0; si < 64; ++si) {
            int pf = si + 2 < 64 ? si + 2 : 63;
            float4 cn = cbase[(size_t)pf * (D_DIM / 4)];

            const __half2 ca = __floats2half2_rn(c0.x, c0.y);
            const __half2 cb = __floats2half2_rn(c0.z, c0.w);

            float acc[T_TILE];
#pragma unroll
            for (int t = 0; t < T_TILE; ++t) {
                __half2 x0 = __hadd2(hh[t][0], ca);
                __half2 x1 = __hadd2(hh[t][1], cb);
                __half2 p0 = __hmul2(tanh2_ap(x0), ww0);
                __half2 p1 = __hmul2(tanh2_ap(x1), ww1);
                float2 ps = __half22float2(__hadd2(p0, p1));
                acc[t] = ps.x + ps.y;
            }

            // merged butterfly: 9 shfl reduce all 4 accumulators
            float r0 = acc[0] + __shfl_xor_sync(0xffffffffu, acc[0], 16);
            float r1 = acc[1] + __shfl_xor_sync(0xffffffffu, acc[1], 16);
            float r2 = acc[2] + __shfl_xor_sync(0xffffffffu, acc[2], 16);
            float r3 = acc[3] + __shfl_xor_sync(0xffffffffu, acc[3], 16);
            float m01 = (lane & 16) ? r1 : r0;
            float m23 = (lane & 16) ? r3 : r2;
            m01 += __shfl_xor_sync(0xffffffffu, m01, 8);
            m23 += __shfl_xor_sync(0xffffffffu, m23, 8);
            float qv = (lane & 8) ? m23 : m01;
            qv += __shfl_xor_sync(0xffffffffu, qv, 4);
            qv += __shfl_xor_sync(0xffffffffu, qv, 2);
            qv += __shfl_xor_sync(0xffffffffu, qv, 1);
            if ((lane & 7) == 0) {
                int t = ((lane >> 4) & 1) + (((lane >> 3) & 1) << 1);
                lg[q][t][sg * 64 + si] = qv;
            }
            c0 = c1; c1 = cn;
        }
    }
    __syncthreads();

    // ---- softmax: warps 0..3, row t = wid (v_b omitted: cancels) ----
    if (wid < T_TILE) {
        const int t = wid;
        float e[8];
        float m = -1e30f;
#pragma unroll
        for (int k = 0; k < 8; ++k) {
            int i = k * 32 + lane;
            e[k] = lg[0][t][i] + lg[1][t][i] + lg[2][t][i] + lg[3][t][i];
            m = fmaxf(m, e[k]);
        }
#pragma unroll
        for (int o = 16; o; o >>= 1) m = fmaxf(m, __shfl_xor_sync(0xffffffffu, m, o));
        float ssum = 0.f;
#pragma unroll
        for (int k = 0; k < 8; ++k) {
            e[k] = __expf(e[k] - m);
            ssum += e[k];
        }
#pragma unroll
        for (int o = 16; o; o >>= 1) ssum += __shfl_xor_sync(0xffffffffu, ssum, o);
        const float inv = 1.0f / ssum;
        float* oa = out_attn + ((size_t)b * T_DIM + t0 + t) * S_DIM;
#pragma unroll
        for (int k = 0; k < 8; ++k)
            oa[k * 32 + lane] = e[k] * inv;
    }
}

// ---------------------------------------------------------------------------
// Kernel 3: weighted = attn @ values, SMEM-staged double-buffered (R11).
// grid=(B, 2, T/8)=256 blocks, 256 thr, 2 CTA/SM.
// ---------------------------------------------------------------------------
__global__ __launch_bounds__(256, 2) void av_kernel(
    const float* __restrict__ values,    // (B,S,D)
    const float* __restrict__ attn,      // (B*T, S) normalized
    float* __restrict__ out_w)           // (T,B,D)
{
    __shared__ float p_s[T_AV][S_DIM];   // 8 KB
    __shared__ float4 vs[2][16][64];     // 32 KB

    const int b   = blockIdx.x;
    const int dh  = blockIdx.y;
    const int t0  = blockIdx.z * T_AV;
    const int tid = threadIdx.x;
    const int tx  = tid & 63;            // d float4 column
    const int ty  = tid >> 6;            // 0..3 -> t pair

    {
        const float4* ap = (const float4*)(attn + ((size_t)b * T_DIM + t0) * S_DIM);
        float4* ps4 = (float4*)p_s;
        for (int i = tid; i < T_AV * S_DIM / 4; i += 256) ps4[i] = ap[i];
    }

    const float4* vp = (const float4*)(values + (size_t)b * S_DIM * D_DIM + dh * 256);
    const int r0 = tid >> 6;

    float acc[2][4];
#pragma unroll
    for (int i = 0; i < 2; ++i)
#pragma unroll
        for (int j = 0; j < 4; ++j) acc[i][j] = 0.f;

    float4 pre[4];
#pragma unroll
    for (int k = 0; k < 4; ++k)
        pre[k] = vp[(size_t)(r0 + k * 4) * (D_DIM / 4) + tx];
#pragma unroll
    for (int k = 0; k < 4; ++k)
        vs[0][r0 + k * 4][tx] = pre[k];
    __syncthreads();

    int buf = 0;
    for (int s0 = 0; s0 < S_DIM; s0 += 16) {
        const bool hn = (s0 + 16) < S_DIM;
        if (hn) {
#pragma unroll
            for (int k = 0; k < 4; ++k)
                pre[k] = vp[(size_t)(s0 + 16 + r0 + k * 4) * (D_DIM / 4) + tx];
        }

#pragma unroll
        for (int s4 = 0; s4 < 4; ++s4) {
            float4 pa4 = *(const float4*)&p_s[ty * 2 + 0][s0 + s4 * 4];
            float4 pb4 = *(const float4*)&p_s[ty * 2 + 1][s0 + s4 * 4];
            const float pa[4] = {pa4.x, pa4.y, pa4.z, pa4.w};
            const float pb[4] = {pb4.x, pb4.y, pb4.z, pb4.w};
#pragma unroll
            for (int ss = 0; ss < 4; ++ss) {
                float4 v = vs[buf][s4 * 4 + ss][tx];
                acc[0][0] += pa[ss] * v.x; acc[0][1] += pa[ss] * v.y;
                acc[0][2] += pa[ss] * v.z; acc[0][3] += pa[ss] * v.w;
                acc[1][0] += pb[ss] * v.x; acc[1][1] += pb[ss] * v.y;
                acc[1][2] += pb[ss] * v.z; acc[1][3] += pb[ss] * v.w;
            }
        }

        if (hn) {
            const int nb = buf ^ 1;
#pragma unroll
            for (int k = 0; k < 4; ++k)
                vs[nb][r0 + k * 4][tx] = pre[k];
        }
        __syncthreads();
        buf ^= 1;
    }

#pragma unroll
    for (int i = 0; i < 2; ++i) {
        const int t = ty * 2 + i;
        float4 o;
        o.x = acc[i][0]; o.y = acc[i][1]; o.z = acc[i][2]; o.w = acc[i][3];
        *(float4*)&out_w[((size_t)(t0 + t) * B_DIM + b) * D_DIM + dh * 256 + tx * 4] = o;
    }
}

// ---------------------------------------------------------------------------
extern "C" void kernel_launch(void* const* d_in, const int* in_sizes, int n_in,
                              void* d_out, int out_size) {
    const float* input   = (const float*)d_in[0];
    const float* context = (const float*)d_in[1];
    const float* values  = (const float*)d_in[2];
    const float* W_comb  = (const float*)d_in[3];
    const float* b_comb  = (const float*)d_in[4];
    const float* v_w     = (const float*)d_in[5];

    float* out_weighted = (float*)d_out;                                 // (T,B,D)
    float* out_attn     = (float*)d_out + (size_t)T_DIM * B_DIM * D_DIM; // (B*T,S)

    dim3 g1(D_DIM / 64, (T_DIM * B_DIM) / 64);           // (8,16)
    gemm_kernel<<<g1, 256>>>(input, W_comb, b_comb);

    dim3 g2(B_DIM, T_DIM / T_TILE);                      // (16,16) = 256 blocks
    logits_kernel<<<g2, 512>>>(context, v_w, out_attn);

    dim3 g3(B_DIM, 2, T_DIM / T_AV);                     // (16,2,8) = 256 blocks
    av_kernel<<<g3, 256>>>(values, out_attn, out_weighted);
}